// round 16
// baseline (speedup 1.0000x reference)
#include <cuda_runtime.h>
#include <cuda_bf16.h>
#include <cstdint>
#include <stdint.h>
#include <math.h>

#define D      128
#define TWO_D  256
#define MTILE  16
#define NTHREADS 256
#define MAXN   50000
#define MAXE   800000

// A image: 16 rows x 256 bf16, row stride 528 bytes (conflict-free LDSM)
#define A_STRIDE 528
#define A_IMG    (16 * A_STRIDE)      // 8448
#define SMEM_AHI 0
#define SMEM_ALO A_IMG
#define SMEM_TOTAL (2 * A_IMG)        // 16896 -> 4 CTAs/SM easily

// ---------------------------------------------------------------------------
// Device globals
// ---------------------------------------------------------------------------
__device__ int   g_base[MAXN + 1];    // per-block-local exclusive scan
__device__ int   g_cursor[MAXN];
__device__ int   g_csr[MAXE];
__device__ int   g_bsum[64];          // block offsets (exclusive)
// Pre-computed mma.sync B fragments (per-lane register images), hi/lo terms.
__device__ uint4 g_B1fh[8192];
__device__ uint4 g_B1fl[8192];
__device__ uint4 g_B2fh[4096];
__device__ uint4 g_B2fl[4096];

// ---------------------------------------------------------------------------
// helpers
// ---------------------------------------------------------------------------
__device__ __forceinline__ uint32_t smem_u32(const void* p) {
    uint32_t a;
    asm("{ .reg .u64 t; cvta.to.shared.u64 t, %1; cvt.u32.u64 %0, t; }" : "=r"(a) : "l"(p));
    return a;
}
__device__ __forceinline__ void ldsm4(uint32_t* r, uint32_t addr) {
    asm volatile("ldmatrix.sync.aligned.m8n8.x4.shared.b16 {%0,%1,%2,%3}, [%4];"
                 : "=r"(r[0]), "=r"(r[1]), "=r"(r[2]), "=r"(r[3]) : "r"(addr));
}
__device__ __forceinline__ void mma16816(float* d, const uint32_t* a, uint32_t b0, uint32_t b1) {
    asm volatile("mma.sync.aligned.m16n8k16.row.col.f32.bf16.bf16.f32 "
                 "{%0,%1,%2,%3}, {%4,%5,%6,%7}, {%8,%9}, {%0,%1,%2,%3};"
                 : "+f"(d[0]), "+f"(d[1]), "+f"(d[2]), "+f"(d[3])
                 : "r"(a[0]), "r"(a[1]), "r"(a[2]), "r"(a[3]), "r"(b0), "r"(b1));
}
__device__ __forceinline__ int a_off(int row, int k) {
    return row * A_STRIDE + ((k >> 3) << 4) + ((k & 7) << 1);
}
__device__ __forceinline__ void split_pair(char* hi_base, char* lo_base, int off,
                                           float v0, float v1) {
    __nv_bfloat16 h0 = __float2bfloat16(v0);
    __nv_bfloat16 h1 = __float2bfloat16(v1);
    __nv_bfloat16 l0 = __float2bfloat16(v0 - __bfloat162float(h0));
    __nv_bfloat16 l1 = __float2bfloat16(v1 - __bfloat162float(h1));
    *reinterpret_cast<__nv_bfloat162*>(hi_base + off) = __halves2bfloat162(h0, h1);
    *reinterpret_cast<__nv_bfloat162*>(lo_base + off) = __halves2bfloat162(l0, l1);
}
__device__ __forceinline__ uint32_t pack_hi(float a, float b) {
    __nv_bfloat162 v = __halves2bfloat162(__float2bfloat16(a), __float2bfloat16(b));
    return *reinterpret_cast<uint32_t*>(&v);
}
__device__ __forceinline__ uint32_t pack_lo(float a, float b) {
    __nv_bfloat16 ha = __float2bfloat16(a), hb = __float2bfloat16(b);
    __nv_bfloat162 v = __halves2bfloat162(__float2bfloat16(a - __bfloat162float(ha)),
                                          __float2bfloat16(b - __bfloat162float(hb)));
    return *reinterpret_cast<uint32_t*>(&v);
}

// ---------------------------------------------------------------------------
// Kernel A (merged): blocks [0,12) -> weight fragment prep
//                    blocks [12, 12+nb) -> per-block scan of degree
// ---------------------------------------------------------------------------
__global__ void prep_scan_kernel(const float* __restrict__ W1,
                                 const float* __restrict__ W2,
                                 const float* __restrict__ degree, int N) {
    const int tid = threadIdx.x;
    if (blockIdx.x < 12) {
        int idx = blockIdx.x * 1024 + tid;
        if (idx < 8192) {
            int lane = idx & 31, ng = (idx >> 5) & 15, ks = idx >> 9;
            int n0 = ng * 16 + (lane >> 2);
            int kb = ks * 16 + (lane & 3) * 2;
            float a0 = W1[(size_t)(kb)     * 256 + n0], a1 = W1[(size_t)(kb + 1) * 256 + n0];
            float a2 = W1[(size_t)(kb + 8) * 256 + n0], a3 = W1[(size_t)(kb + 9) * 256 + n0];
            float a4 = W1[(size_t)(kb)     * 256 + n0 + 8], a5 = W1[(size_t)(kb + 1) * 256 + n0 + 8];
            float a6 = W1[(size_t)(kb + 8) * 256 + n0 + 8], a7 = W1[(size_t)(kb + 9) * 256 + n0 + 8];
            g_B1fh[idx] = make_uint4(pack_hi(a0, a1), pack_hi(a2, a3), pack_hi(a4, a5), pack_hi(a6, a7));
            g_B1fl[idx] = make_uint4(pack_lo(a0, a1), pack_lo(a2, a3), pack_lo(a4, a5), pack_lo(a6, a7));
        } else if (idx < 12288) {
            int i2 = idx - 8192;
            int lane = i2 & 31, ng = (i2 >> 5) & 7, ks = i2 >> 8;
            int n0 = ng * 16 + (lane >> 2);
            int kb = ks * 16 + (lane & 3) * 2;
            float a0 = W2[(size_t)(kb)     * 128 + n0], a1 = W2[(size_t)(kb + 1) * 128 + n0];
            float a2 = W2[(size_t)(kb + 8) * 128 + n0], a3 = W2[(size_t)(kb + 9) * 128 + n0];
            float a4 = W2[(size_t)(kb)     * 128 + n0 + 8], a5 = W2[(size_t)(kb + 1) * 128 + n0 + 8];
            float a6 = W2[(size_t)(kb + 8) * 128 + n0 + 8], a7 = W2[(size_t)(kb + 9) * 128 + n0 + 8];
            g_B2fh[i2] = make_uint4(pack_hi(a0, a1), pack_hi(a2, a3), pack_hi(a4, a5), pack_hi(a6, a7));
            g_B2fl[i2] = make_uint4(pack_lo(a0, a1), pack_lo(a2, a3), pack_lo(a4, a5), pack_lo(a6, a7));
        }
        return;
    }
    __shared__ int warp_sums[32];
    const int bid = blockIdx.x - 12;
    const int lane = tid & 31, wid = tid >> 5;
    const int i = bid * 1024 + tid;
    int v = (i < N) ? (int)degree[i] : 0;
    int inc = v;
#pragma unroll
    for (int o = 1; o < 32; o <<= 1) {
        int t = __shfl_up_sync(0xffffffffu, inc, o);
        if (lane >= o) inc += t;
    }
    if (lane == 31) warp_sums[wid] = inc;
    __syncthreads();
    if (wid == 0) {
        int ws = warp_sums[lane];
#pragma unroll
        for (int o = 1; o < 32; o <<= 1) {
            int t = __shfl_up_sync(0xffffffffu, ws, o);
            if (lane >= o) ws += t;
        }
        warp_sums[lane] = ws;
    }
    __syncthreads();
    int excl = (wid > 0 ? warp_sums[wid - 1] : 0) + inc - v;
    if (i < N) { g_base[i] = excl; g_cursor[i] = 0; }
    if (tid == 1023) g_bsum[bid] = warp_sums[31];
}

// Kernel B: scan block sums (1 block, 64 threads, nb <= 64)
__global__ void scan2_kernel(int nb) {
    const int tid = threadIdx.x, lane = tid & 31, wid = tid >> 5;
    __shared__ int ws2[2];
    int v = (tid < nb) ? g_bsum[tid] : 0;
    int inc = v;
#pragma unroll
    for (int o = 1; o < 32; o <<= 1) {
        int t = __shfl_up_sync(0xffffffffu, inc, o);
        if (lane >= o) inc += t;
    }
    if (lane == 31) ws2[wid] = inc;
    __syncthreads();
    int excl = inc - v + (wid > 0 ? ws2[0] : 0);
    if (tid < nb) g_bsum[tid] = excl;
}

// Kernel C: CSR fill (adds block offset inline)
__global__ void fill_kernel(const int* __restrict__ esrc,
                            const int* __restrict__ edst, int E) {
    int e = blockIdx.x * blockDim.x + threadIdx.x;
    if (e >= E) return;
    int t = edst[e];
    int pos = g_base[t] + g_bsum[t >> 10] + atomicAdd(&g_cursor[t], 1);
    if (pos < MAXE) g_csr[pos] = esrc[e];
}

// ---------------------------------------------------------------------------
// Fused kernel: CSR-gather + LN(x) + LN(neighbor) -> split-bf16 mma GEMM1
//               -> GELU -> GEMM2 -> bias + residual.
// 16 rows/CTA (one m16 MMA covers all rows), 8 warps all in N.
// Warp tile 16x32 (GEMM1) / 16x16 (GEMM2) -> ~64 regs -> 4 CTAs/SM (32 warps).
// ---------------------------------------------------------------------------
__global__ void __launch_bounds__(NTHREADS, 4)
fused_kernel(const float* __restrict__ x,
             const float* __restrict__ degree,
             const float* __restrict__ sn_g, const float* __restrict__ sn_b,
             const float* __restrict__ nn_g, const float* __restrict__ nn_b,
             const float* __restrict__ b1,  const float* __restrict__ b2,
             float* __restrict__ out, int N, int nrows) {
    extern __shared__ char sm[];
    const uint32_t smem_base = smem_u32(sm);
    char* Ahi = sm + SMEM_AHI;
    char* Alo = sm + SMEM_ALO;

    const int tid  = threadIdx.x;
    const int lane = tid & 31;
    const int warp = tid >> 5;      // 0..7 = N group
    const int wn   = warp;
    const int row0 = blockIdx.x * MTILE;
    const int g    = lane >> 3;
    const int lr   = lane & 7;

    // ---------------- Stage 1: gather + LayerNorms -> A images --------------
    {
        const float4 g1  = *reinterpret_cast<const float4*>(sn_g + lane * 4);
        const float4 be1 = *reinterpret_cast<const float4*>(sn_b + lane * 4);
        const float4 g2  = *reinterpret_cast<const float4*>(nn_g + lane * 4);
        const float4 be2 = *reinterpret_cast<const float4*>(nn_b + lane * 4);
        const int k0 = lane * 4;
#pragma unroll
        for (int rr = 0; rr < 2; rr++) {
            const int r    = warp * 2 + rr;   // 0..15
            const int grow = row0 + r;
            if (grow < nrows) {
                // ---- LN(x) ----
                float4 xv = *reinterpret_cast<const float4*>(x + (size_t)grow * D + k0);
                float sum  = xv.x + xv.y + xv.z + xv.w;
                float sumq = xv.x * xv.x + xv.y * xv.y + xv.z * xv.z + xv.w * xv.w;
#pragma unroll
                for (int o = 16; o > 0; o >>= 1) {
                    sum  += __shfl_xor_sync(0xffffffffu, sum, o);
                    sumq += __shfl_xor_sync(0xffffffffu, sumq, o);
                }
                float mn   = sum * (1.0f / 128.0f);
                float rstd = rsqrtf(sumq * (1.0f / 128.0f) - mn * mn + 1e-5f);
                split_pair(Ahi, Alo, a_off(r, k0),     (xv.x - mn) * rstd * g1.x + be1.x,
                                                       (xv.y - mn) * rstd * g1.y + be1.y);
                split_pair(Ahi, Alo, a_off(r, k0 + 2), (xv.z - mn) * rstd * g1.z + be1.z,
                                                       (xv.w - mn) * rstd * g1.w + be1.w);

                // ---- CSR gather of neighbors (4-wide unroll, 2 accumulators)
                int node = grow, boff = 0;
                if (grow >= N) { node = grow - N; boff = N; }
                const float dgf = degree[node];
                const int   deg = (int)dgf;
                const float inv = 1.0f / fmaxf(dgf, 1.0f);
                const int   bs  = g_base[node] + g_bsum[node >> 10];
                float4 nva = make_float4(0.f, 0.f, 0.f, 0.f);
                float4 nvb = make_float4(0.f, 0.f, 0.f, 0.f);
                int j = 0;
                for (; j + 4 <= deg; j += 4) {
                    int s0 = g_csr[bs + j],     s1 = g_csr[bs + j + 1];
                    int s2 = g_csr[bs + j + 2], s3 = g_csr[bs + j + 3];
                    const float4 v0 = *reinterpret_cast<const float4*>(
                        x + ((size_t)(boff + s0)) * D + k0);
                    const float4 v1 = *reinterpret_cast<const float4*>(
                        x + ((size_t)(boff + s1)) * D + k0);
                    const float4 v2 = *reinterpret_cast<const float4*>(
                        x + ((size_t)(boff + s2)) * D + k0);
                    const float4 v3 = *reinterpret_cast<const float4*>(
                        x + ((size_t)(boff + s3)) * D + k0);
                    nva.x += v0.x + v1.x; nva.y += v0.y + v1.y;
                    nva.z += v0.z + v1.z; nva.w += v0.w + v1.w;
                    nvb.x += v2.x + v3.x; nvb.y += v2.y + v3.y;
                    nvb.z += v2.z + v3.z; nvb.w += v2.w + v3.w;
                }
                for (; j < deg; j++) {
                    int s0 = g_csr[bs + j];
                    const float4 v0 = *reinterpret_cast<const float4*>(
                        x + ((size_t)(boff + s0)) * D + k0);
                    nva.x += v0.x; nva.y += v0.y; nva.z += v0.z; nva.w += v0.w;
                }
                float4 nv;
                nv.x = (nva.x + nvb.x) * inv;
                nv.y = (nva.y + nvb.y) * inv;
                nv.z = (nva.z + nvb.z) * inv;
                nv.w = (nva.w + nvb.w) * inv;

                // ---- LN(neighbor) ----
                sum  = nv.x + nv.y + nv.z + nv.w;
                sumq = nv.x * nv.x + nv.y * nv.y + nv.z * nv.z + nv.w * nv.w;
#pragma unroll
                for (int o = 16; o > 0; o >>= 1) {
                    sum  += __shfl_xor_sync(0xffffffffu, sum, o);
                    sumq += __shfl_xor_sync(0xffffffffu, sumq, o);
                }
                mn   = sum * (1.0f / 128.0f);
                rstd = rsqrtf(sumq * (1.0f / 128.0f) - mn * mn + 1e-5f);
                split_pair(Ahi, Alo, a_off(r, 128 + k0),     (nv.x - mn) * rstd * g2.x + be2.x,
                                                             (nv.y - mn) * rstd * g2.y + be2.y);
                split_pair(Ahi, Alo, a_off(r, 128 + k0 + 2), (nv.z - mn) * rstd * g2.z + be2.z,
                                                             (nv.w - mn) * rstd * g2.w + be2.w);
            } else {
                split_pair(Ahi, Alo, a_off(r, k0),           0.f, 0.f);
                split_pair(Ahi, Alo, a_off(r, k0 + 2),       0.f, 0.f);
                split_pair(Ahi, Alo, a_off(r, 128 + k0),     0.f, 0.f);
                split_pair(Ahi, Alo, a_off(r, 128 + k0 + 2), 0.f, 0.f);
            }
        }
    }
    __syncthreads();

    // ---------------- Stage 2: GEMM1 (16 x 32-per-warp x 256, 3 terms) ------
    float acc[4][4];        // [col-tile of 8][4] = 16 regs
#pragma unroll
    for (int j = 0; j < 4; j++)
#pragma unroll
        for (int r = 0; r < 4; r++) acc[j][r] = 0.f;

#pragma unroll 2
    for (int ks = 0; ks < 16; ks++) {
        const int kabs = ks * 16;
        uint32_t ahi[4], alo[4];
        {
            int row = (g & 1) * 8 + lr;
            uint32_t off = row * A_STRIDE + (((kabs >> 3) + (g >> 1)) << 4);
            ldsm4(ahi, smem_base + SMEM_AHI + off);
            ldsm4(alo, smem_base + SMEM_ALO + off);
        }
#pragma unroll
        for (int jj = 0; jj < 2; jj++) {
            const int fi = (ks * 16 + wn * 2 + jj) * 32 + lane;
            const uint4 fh = g_B1fh[fi];
            const uint4 fl = g_B1fl[fi];
            mma16816(acc[2 * jj],     ahi, fh.x, fh.y);
            mma16816(acc[2 * jj],     ahi, fl.x, fl.y);
            mma16816(acc[2 * jj],     alo, fh.x, fh.y);
            mma16816(acc[2 * jj + 1], ahi, fh.z, fh.w);
            mma16816(acc[2 * jj + 1], ahi, fl.z, fl.w);
            mma16816(acc[2 * jj + 1], alo, fh.z, fh.w);
        }
    }

    // ---------------- Stage 3: bias + GELU -> A2 images ---------------------
    __syncthreads();
#pragma unroll
    for (int tj = 0; tj < 4; tj++) {
        const int col = wn * 32 + tj * 8 + (lane & 3) * 2;
        const float2 bb = *reinterpret_cast<const float2*>(b1 + col);
#pragma unroll
        for (int rp = 0; rp < 2; rp++) {
            int row = (lane >> 2) + rp * 8;
            float v0 = acc[tj][rp * 2 + 0] + bb.x;
            float v1 = acc[tj][rp * 2 + 1] + bb.y;
            v0 = 0.5f * v0 * (1.0f + erff(v0 * 0.70710678118654752f));
            v1 = 0.5f * v1 * (1.0f + erff(v1 * 0.70710678118654752f));
            split_pair(Ahi, Alo, a_off(row, col), v0, v1);
        }
    }
    __syncthreads();

    // ---------------- Stage 4: GEMM2 (16 x 16-per-warp x 256, 3 terms) ------
    float c2[2][4];         // 8 regs
#pragma unroll
    for (int j = 0; j < 2; j++)
#pragma unroll
        for (int r = 0; r < 4; r++) c2[j][r] = 0.f;

#pragma unroll 2
    for (int ks = 0; ks < 16; ks++) {
        const int kabs = ks * 16;
        uint32_t ahi[4], alo[4];
        {
            int row = (g & 1) * 8 + lr;
            uint32_t off = row * A_STRIDE + (((kabs >> 3) + (g >> 1)) << 4);
            ldsm4(ahi, smem_base + SMEM_AHI + off);
            ldsm4(alo, smem_base + SMEM_ALO + off);
        }
        {
            const int fi = (ks * 8 + wn) * 32 + lane;
            const uint4 fh = g_B2fh[fi];
            const uint4 fl = g_B2fl[fi];
            mma16816(c2[0], ahi, fh.x, fh.y);
            mma16816(c2[0], ahi, fl.x, fl.y);
            mma16816(c2[0], alo, fh.x, fh.y);
            mma16816(c2[1], ahi, fh.z, fh.w);
            mma16816(c2[1], ahi, fl.z, fl.w);
            mma16816(c2[1], alo, fh.z, fh.w);
        }
    }

    // ---------------- Stage 5: bias + residual + store ----------------------
#pragma unroll
    for (int tj = 0; tj < 2; tj++) {
        const int col = wn * 16 + tj * 8 + (lane & 3) * 2;
        const float2 bb = *reinterpret_cast<const float2*>(b2 + col);
#pragma unroll
        for (int rp = 0; rp < 2; rp++) {
            int row  = (lane >> 2) + rp * 8;
            int grow = row0 + row;
            if (grow < nrows) {
                const float2 xv = *reinterpret_cast<const float2*>(x + (size_t)grow * D + col);
                float2 o;
                o.x = xv.x + c2[tj][rp * 2 + 0] + bb.x;
                o.y = xv.y + c2[tj][rp * 2 + 1] + bb.y;
                *reinterpret_cast<float2*>(out + (size_t)grow * D + col) = o;
            }
        }
    }
}

// ---------------------------------------------------------------------------
extern "C" void kernel_launch(void* const* d_in, const int* in_sizes, int n_in,
                              void* d_out, int out_size) {
    const float* x      = (const float*)d_in[0];
    const int*   esrc   = (const int*)  d_in[1];
    const int*   edst   = (const int*)  d_in[2];
    const float* degree = (const float*)d_in[3];
    const float* sn_g   = (const float*)d_in[4];
    const float* sn_b   = (const float*)d_in[5];
    const float* nn_g   = (const float*)d_in[6];
    const float* nn_b   = (const float*)d_in[7];
    const float* W1     = (const float*)d_in[8];
    const float* b1     = (const float*)d_in[9];
    const float* W2     = (const float*)d_in[10];
    const float* b2     = (const float*)d_in[11];

    const int E     = in_sizes[1];
    const int nrows = in_sizes[0] / D;   // B*N
    const int N     = in_sizes[3];
    const int nb    = (N + 1023) / 1024;

    prep_scan_kernel<<<12 + nb, 1024>>>(W1, W2, degree, N);
    scan2_kernel<<<1, 64>>>(nb);
    fill_kernel<<<(E + 255) / 256, 256>>>(esrc, edst, E);

    cudaFuncSetAttribute(fused_kernel, cudaFuncAttributeMaxDynamicSharedMemorySize, SMEM_TOTAL);
    fused_kernel<<<(nrows + MTILE - 1) / MTILE, NTHREADS, SMEM_TOTAL>>>(
        x, degree, sn_g, sn_b, nn_g, nn_b, b1, b2, (float*)d_out, N, nrows);
}

// round 17
// speedup vs baseline: 1.1907x; 1.1907x over previous
#include <cuda_runtime.h>
#include <cuda_fp16.h>
#include <cstdint>
#include <stdint.h>
#include <math.h>

#define D      128
#define TWO_D  256
#define MTILE  32
#define NTHREADS 256
#define MAXN   50000
#define MAXE   800000

// A image (single, fp16): 32 rows x 256 halves, row stride 528B (conflict-free LDSM)
#define A_STRIDE 528
#define A_IMG    (32 * A_STRIDE)      // 16896
#define SMEM_TOTAL A_IMG              // 16.9KB -> 4 CTAs/SM trivially smem-wise

// ---------------------------------------------------------------------------
// Device globals
// ---------------------------------------------------------------------------
__device__ int   g_base[MAXN + 1];
__device__ int   g_cursor[MAXN];
__device__ int   g_csr[MAXE];
__device__ int   g_bsum[64];
// Pre-computed mma.sync B fragments (per-lane register images), fp16 hi/lo split.
__device__ uint4 g_B1fh[8192];
__device__ uint4 g_B1fl[8192];
__device__ uint4 g_B2fh[4096];
__device__ uint4 g_B2fl[4096];

// ---------------------------------------------------------------------------
// helpers
// ---------------------------------------------------------------------------
__device__ __forceinline__ uint32_t smem_u32(const void* p) {
    uint32_t a;
    asm("{ .reg .u64 t; cvta.to.shared.u64 t, %1; cvt.u32.u64 %0, t; }" : "=r"(a) : "l"(p));
    return a;
}
__device__ __forceinline__ void ldsm4(uint32_t* r, uint32_t addr) {
    asm volatile("ldmatrix.sync.aligned.m8n8.x4.shared.b16 {%0,%1,%2,%3}, [%4];"
                 : "=r"(r[0]), "=r"(r[1]), "=r"(r[2]), "=r"(r[3]) : "r"(addr));
}
__device__ __forceinline__ void mma16816(float* d, const uint32_t* a, uint32_t b0, uint32_t b1) {
    asm volatile("mma.sync.aligned.m16n8k16.row.col.f32.f16.f16.f32 "
                 "{%0,%1,%2,%3}, {%4,%5,%6,%7}, {%8,%9}, {%0,%1,%2,%3};"
                 : "+f"(d[0]), "+f"(d[1]), "+f"(d[2]), "+f"(d[3])
                 : "r"(a[0]), "r"(a[1]), "r"(a[2]), "r"(a[3]), "r"(b0), "r"(b1));
}
__device__ __forceinline__ int a_off(int row, int k) {
    return row * A_STRIDE + ((k >> 3) << 4) + ((k & 7) << 1);
}
__device__ __forceinline__ void store2(char* base, int off, float v0, float v1) {
    *reinterpret_cast<__half2*>(base + off) = __floats2half2_rn(v0, v1);
}
__device__ __forceinline__ uint32_t pack_hi(float a, float b) {
    __half2 v = __halves2half2(__float2half_rn(a), __float2half_rn(b));
    return *reinterpret_cast<uint32_t*>(&v);
}
__device__ __forceinline__ uint32_t pack_lo(float a, float b) {
    __half ha = __float2half_rn(a), hb = __float2half_rn(b);
    __half2 v = __halves2half2(__float2half_rn(a - __half2float(ha)),
                               __float2half_rn(b - __half2float(hb)));
    return *reinterpret_cast<uint32_t*>(&v);
}

// ---------------------------------------------------------------------------
// Kernel A (merged): blocks [0,12) -> weight fragment prep (fp16 split)
//                    blocks [12, 12+nb) -> per-block scan of degree
// ---------------------------------------------------------------------------
__global__ void prep_scan_kernel(const float* __restrict__ W1,
                                 const float* __restrict__ W2,
                                 const float* __restrict__ degree, int N) {
    const int tid = threadIdx.x;
    if (blockIdx.x < 12) {
        int idx = blockIdx.x * 1024 + tid;
        if (idx < 8192) {
            int lane = idx & 31, ng = (idx >> 5) & 15, ks = idx >> 9;
            int n0 = ng * 16 + (lane >> 2);
            int kb = ks * 16 + (lane & 3) * 2;
            float a0 = W1[(size_t)(kb)     * 256 + n0], a1 = W1[(size_t)(kb + 1) * 256 + n0];
            float a2 = W1[(size_t)(kb + 8) * 256 + n0], a3 = W1[(size_t)(kb + 9) * 256 + n0];
            float a4 = W1[(size_t)(kb)     * 256 + n0 + 8], a5 = W1[(size_t)(kb + 1) * 256 + n0 + 8];
            float a6 = W1[(size_t)(kb + 8) * 256 + n0 + 8], a7 = W1[(size_t)(kb + 9) * 256 + n0 + 8];
            g_B1fh[idx] = make_uint4(pack_hi(a0, a1), pack_hi(a2, a3), pack_hi(a4, a5), pack_hi(a6, a7));
            g_B1fl[idx] = make_uint4(pack_lo(a0, a1), pack_lo(a2, a3), pack_lo(a4, a5), pack_lo(a6, a7));
        } else if (idx < 12288) {
            int i2 = idx - 8192;
            int lane = i2 & 31, ng = (i2 >> 5) & 7, ks = i2 >> 8;
            int n0 = ng * 16 + (lane >> 2);
            int kb = ks * 16 + (lane & 3) * 2;
            float a0 = W2[(size_t)(kb)     * 128 + n0], a1 = W2[(size_t)(kb + 1) * 128 + n0];
            float a2 = W2[(size_t)(kb + 8) * 128 + n0], a3 = W2[(size_t)(kb + 9) * 128 + n0];
            float a4 = W2[(size_t)(kb)     * 128 + n0 + 8], a5 = W2[(size_t)(kb + 1) * 128 + n0 + 8];
            float a6 = W2[(size_t)(kb + 8) * 128 + n0 + 8], a7 = W2[(size_t)(kb + 9) * 128 + n0 + 8];
            g_B2fh[i2] = make_uint4(pack_hi(a0, a1), pack_hi(a2, a3), pack_hi(a4, a5), pack_hi(a6, a7));
            g_B2fl[i2] = make_uint4(pack_lo(a0, a1), pack_lo(a2, a3), pack_lo(a4, a5), pack_lo(a6, a7));
        }
        return;
    }
    __shared__ int warp_sums[32];
    const int bid = blockIdx.x - 12;
    const int lane = tid & 31, wid = tid >> 5;
    const int i = bid * 1024 + tid;
    int v = (i < N) ? (int)degree[i] : 0;
    int inc = v;
#pragma unroll
    for (int o = 1; o < 32; o <<= 1) {
        int t = __shfl_up_sync(0xffffffffu, inc, o);
        if (lane >= o) inc += t;
    }
    if (lane == 31) warp_sums[wid] = inc;
    __syncthreads();
    if (wid == 0) {
        int ws = warp_sums[lane];
#pragma unroll
        for (int o = 1; o < 32; o <<= 1) {
            int t = __shfl_up_sync(0xffffffffu, ws, o);
            if (lane >= o) ws += t;
        }
        warp_sums[lane] = ws;
    }
    __syncthreads();
    int excl = (wid > 0 ? warp_sums[wid - 1] : 0) + inc - v;
    if (i < N) { g_base[i] = excl; g_cursor[i] = 0; }
    if (tid == 1023) g_bsum[bid] = warp_sums[31];
}

// Kernel B: scan block sums (1 block, 64 threads, nb <= 64)
__global__ void scan2_kernel(int nb) {
    const int tid = threadIdx.x, lane = tid & 31, wid = tid >> 5;
    __shared__ int ws2[2];
    int v = (tid < nb) ? g_bsum[tid] : 0;
    int inc = v;
#pragma unroll
    for (int o = 1; o < 32; o <<= 1) {
        int t = __shfl_up_sync(0xffffffffu, inc, o);
        if (lane >= o) inc += t;
    }
    if (lane == 31) ws2[wid] = inc;
    __syncthreads();
    int excl = inc - v + (wid > 0 ? ws2[0] : 0);
    if (tid < nb) g_bsum[tid] = excl;
}

// Kernel C: CSR fill (adds block offset inline)
__global__ void fill_kernel(const int* __restrict__ esrc,
                            const int* __restrict__ edst, int E) {
    int e = blockIdx.x * blockDim.x + threadIdx.x;
    if (e >= E) return;
    int t = edst[e];
    int pos = g_base[t] + g_bsum[t >> 10] + atomicAdd(&g_cursor[t], 1);
    if (pos < MAXE) g_csr[pos] = esrc[e];
}

// ---------------------------------------------------------------------------
// Fused kernel: CSR-gather + LN(x) + LN(neighbor) -> fp16 2-term mma GEMM1
//               -> GELU -> GEMM2 -> bias + residual.
// 32 rows/CTA, 8 warps all in N (warp tile 32x32 / 32x16). Single fp16 A image.
// 2-term split: A fp16 (exact-ish to 2^-11), B = Bhi + Blo fp16.
// ---------------------------------------------------------------------------
__global__ void __launch_bounds__(NTHREADS, 4)
fused_kernel(const float* __restrict__ x,
             const float* __restrict__ degree,
             const float* __restrict__ sn_g, const float* __restrict__ sn_b,
             const float* __restrict__ nn_g, const float* __restrict__ nn_b,
             const float* __restrict__ b1,  const float* __restrict__ b2,
             float* __restrict__ out, int N, int nrows) {
    extern __shared__ char sm[];
    const uint32_t smem_base = smem_u32(sm);
    char* A = sm;

    const int tid  = threadIdx.x;
    const int lane = tid & 31;
    const int warp = tid >> 5;      // 0..7 = N group
    const int wn   = warp;
    const int row0 = blockIdx.x * MTILE;
    const int g    = lane >> 3;
    const int lr   = lane & 7;

    // ---------------- Stage 1: gather + LayerNorms -> A image ---------------
    {
        const float4 g1  = *reinterpret_cast<const float4*>(sn_g + lane * 4);
        const float4 be1 = *reinterpret_cast<const float4*>(sn_b + lane * 4);
        const float4 g2  = *reinterpret_cast<const float4*>(nn_g + lane * 4);
        const float4 be2 = *reinterpret_cast<const float4*>(nn_b + lane * 4);
        const int k0 = lane * 4;
#pragma unroll
        for (int rr = 0; rr < 4; rr++) {
            const int r    = warp * 4 + rr;   // 0..31
            const int grow = row0 + r;
            if (grow < nrows) {
                // ---- LN(x) ----
                float4 xv = *reinterpret_cast<const float4*>(x + (size_t)grow * D + k0);
                float sum  = xv.x + xv.y + xv.z + xv.w;
                float sumq = xv.x * xv.x + xv.y * xv.y + xv.z * xv.z + xv.w * xv.w;
#pragma unroll
                for (int o = 16; o > 0; o >>= 1) {
                    sum  += __shfl_xor_sync(0xffffffffu, sum, o);
                    sumq += __shfl_xor_sync(0xffffffffu, sumq, o);
                }
                float mn   = sum * (1.0f / 128.0f);
                float rstd = rsqrtf(sumq * (1.0f / 128.0f) - mn * mn + 1e-5f);
                store2(A, a_off(r, k0),     (xv.x - mn) * rstd * g1.x + be1.x,
                                            (xv.y - mn) * rstd * g1.y + be1.y);
                store2(A, a_off(r, k0 + 2), (xv.z - mn) * rstd * g1.z + be1.z,
                                            (xv.w - mn) * rstd * g1.w + be1.w);

                // ---- CSR gather of neighbors (4-wide unroll, 2 accumulators)
                int node = grow, boff = 0;
                if (grow >= N) { node = grow - N; boff = N; }
                const float dgf = degree[node];
                const int   deg = (int)dgf;
                const float inv = 1.0f / fmaxf(dgf, 1.0f);
                const int   bs  = g_base[node] + g_bsum[node >> 10];
                float4 nva = make_float4(0.f, 0.f, 0.f, 0.f);
                float4 nvb = make_float4(0.f, 0.f, 0.f, 0.f);
                int j = 0;
                for (; j + 4 <= deg; j += 4) {
                    int s0 = g_csr[bs + j],     s1 = g_csr[bs + j + 1];
                    int s2 = g_csr[bs + j + 2], s3 = g_csr[bs + j + 3];
                    const float4 v0 = *reinterpret_cast<const float4*>(
                        x + ((size_t)(boff + s0)) * D + k0);
                    const float4 v1 = *reinterpret_cast<const float4*>(
                        x + ((size_t)(boff + s1)) * D + k0);
                    const float4 v2 = *reinterpret_cast<const float4*>(
                        x + ((size_t)(boff + s2)) * D + k0);
                    const float4 v3 = *reinterpret_cast<const float4*>(
                        x + ((size_t)(boff + s3)) * D + k0);
                    nva.x += v0.x + v1.x; nva.y += v0.y + v1.y;
                    nva.z += v0.z + v1.z; nva.w += v0.w + v1.w;
                    nvb.x += v2.x + v3.x; nvb.y += v2.y + v3.y;
                    nvb.z += v2.z + v3.z; nvb.w += v2.w + v3.w;
                }
                for (; j < deg; j++) {
                    int s0 = g_csr[bs + j];
                    const float4 v0 = *reinterpret_cast<const float4*>(
                        x + ((size_t)(boff + s0)) * D + k0);
                    nva.x += v0.x; nva.y += v0.y; nva.z += v0.z; nva.w += v0.w;
                }
                float4 nv;
                nv.x = (nva.x + nvb.x) * inv;
                nv.y = (nva.y + nvb.y) * inv;
                nv.z = (nva.z + nvb.z) * inv;
                nv.w = (nva.w + nvb.w) * inv;

                // ---- LN(neighbor) ----
                sum  = nv.x + nv.y + nv.z + nv.w;
                sumq = nv.x * nv.x + nv.y * nv.y + nv.z * nv.z + nv.w * nv.w;
#pragma unroll
                for (int o = 16; o > 0; o >>= 1) {
                    sum  += __shfl_xor_sync(0xffffffffu, sum, o);
                    sumq += __shfl_xor_sync(0xffffffffu, sumq, o);
                }
                mn   = sum * (1.0f / 128.0f);
                rstd = rsqrtf(sumq * (1.0f / 128.0f) - mn * mn + 1e-5f);
                store2(A, a_off(r, 128 + k0),     (nv.x - mn) * rstd * g2.x + be2.x,
                                                  (nv.y - mn) * rstd * g2.y + be2.y);
                store2(A, a_off(r, 128 + k0 + 2), (nv.z - mn) * rstd * g2.z + be2.z,
                                                  (nv.w - mn) * rstd * g2.w + be2.w);
            } else {
                store2(A, a_off(r, k0),           0.f, 0.f);
                store2(A, a_off(r, k0 + 2),       0.f, 0.f);
                store2(A, a_off(r, 128 + k0),     0.f, 0.f);
                store2(A, a_off(r, 128 + k0 + 2), 0.f, 0.f);
            }
        }
    }
    __syncthreads();

    // ---------------- Stage 2: GEMM1 (32 x 32-per-warp x 256, 2 terms) ------
    float acc[2][4][4];     // 32 regs
#pragma unroll
    for (int i = 0; i < 2; i++)
#pragma unroll
        for (int j = 0; j < 4; j++)
#pragma unroll
            for (int r = 0; r < 4; r++) acc[i][j][r] = 0.f;

#pragma unroll 2
    for (int ks = 0; ks < 16; ks++) {
        const int kabs = ks * 16;
        uint32_t a0[4], a1[4];
        {
            int row0l = (g & 1) * 8 + lr;
            uint32_t off0 = row0l * A_STRIDE + (((kabs >> 3) + (g >> 1)) << 4);
            ldsm4(a0, smem_base + off0);
            uint32_t off1 = (16 + row0l) * A_STRIDE + (((kabs >> 3) + (g >> 1)) << 4);
            ldsm4(a1, smem_base + off1);
        }
#pragma unroll
        for (int jj = 0; jj < 2; jj++) {
            const int fi = (ks * 16 + wn * 2 + jj) * 32 + lane;
            const uint4 fh = g_B1fh[fi];
            const uint4 fl = g_B1fl[fi];
            mma16816(acc[0][2 * jj],     a0, fh.x, fh.y);
            mma16816(acc[0][2 * jj],     a0, fl.x, fl.y);
            mma16816(acc[0][2 * jj + 1], a0, fh.z, fh.w);
            mma16816(acc[0][2 * jj + 1], a0, fl.z, fl.w);
            mma16816(acc[1][2 * jj],     a1, fh.x, fh.y);
            mma16816(acc[1][2 * jj],     a1, fl.x, fl.y);
            mma16816(acc[1][2 * jj + 1], a1, fh.z, fh.w);
            mma16816(acc[1][2 * jj + 1], a1, fl.z, fl.w);
        }
    }

    // ---------------- Stage 3: bias + GELU -> A2 image ----------------------
    __syncthreads();
#pragma unroll
    for (int tj = 0; tj < 4; tj++) {
        const int col = wn * 32 + tj * 8 + (lane & 3) * 2;
        const float2 bb = *reinterpret_cast<const float2*>(b1 + col);
#pragma unroll
        for (int ti = 0; ti < 2; ti++)
#pragma unroll
            for (int rp = 0; rp < 2; rp++) {
                int row = ti * 16 + (lane >> 2) + rp * 8;
                float v0 = acc[ti][tj][rp * 2 + 0] + bb.x;
                float v1 = acc[ti][tj][rp * 2 + 1] + bb.y;
                v0 = 0.5f * v0 * (1.0f + erff(v0 * 0.70710678118654752f));
                v1 = 0.5f * v1 * (1.0f + erff(v1 * 0.70710678118654752f));
                store2(A, a_off(row, col), v0, v1);
            }
    }
    __syncthreads();

    // ---------------- Stage 4: GEMM2 (32 x 16-per-warp x 256, 2 terms) ------
    float c2[2][2][4];      // 16 regs
#pragma unroll
    for (int i = 0; i < 2; i++)
#pragma unroll
        for (int j = 0; j < 2; j++)
#pragma unroll
            for (int r = 0; r < 4; r++) c2[i][j][r] = 0.f;

#pragma unroll 2
    for (int ks = 0; ks < 16; ks++) {
        const int kabs = ks * 16;
        uint32_t a0[4], a1[4];
        {
            int row0l = (g & 1) * 8 + lr;
            uint32_t off0 = row0l * A_STRIDE + (((kabs >> 3) + (g >> 1)) << 4);
            ldsm4(a0, smem_base + off0);
            uint32_t off1 = (16 + row0l) * A_STRIDE + (((kabs >> 3) + (g >> 1)) << 4);
            ldsm4(a1, smem_base + off1);
        }
        {
            const int fi = (ks * 8 + wn) * 32 + lane;
            const uint4 fh = g_B2fh[fi];
            const uint4 fl = g_B2fl[fi];
            mma16816(c2[0][0], a0, fh.x, fh.y);
            mma16816(c2[0][0], a0, fl.x, fl.y);
            mma16816(c2[0][1], a0, fh.z, fh.w);
            mma16816(c2[0][1], a0, fl.z, fl.w);
            mma16816(c2[1][0], a1, fh.x, fh.y);
            mma16816(c2[1][0], a1, fl.x, fl.y);
            mma16816(c2[1][1], a1, fh.z, fh.w);
            mma16816(c2[1][1], a1, fl.z, fl.w);
        }
    }

    // ---------------- Stage 5: bias + residual + store ----------------------
#pragma unroll
    for (int tj = 0; tj < 2; tj++) {
        const int col = wn * 16 + tj * 8 + (lane & 3) * 2;
        const float2 bb = *reinterpret_cast<const float2*>(b2 + col);
#pragma unroll
        for (int ti = 0; ti < 2; ti++)
#pragma unroll
            for (int rp = 0; rp < 2; rp++) {
                int row  = ti * 16 + (lane >> 2) + rp * 8;
                int grow = row0 + row;
                if (grow < nrows) {
                    const float2 xv = *reinterpret_cast<const float2*>(x + (size_t)grow * D + col);
                    float2 o;
                    o.x = xv.x + c2[ti][tj][rp * 2 + 0] + bb.x;
                    o.y = xv.y + c2[ti][tj][rp * 2 + 1] + bb.y;
                    *reinterpret_cast<float2*>(out + (size_t)grow * D + col) = o;
                }
            }
    }
}

// ---------------------------------------------------------------------------
extern "C" void kernel_launch(void* const* d_in, const int* in_sizes, int n_in,
                              void* d_out, int out_size) {
    const float* x      = (const float*)d_in[0];
    const int*   esrc   = (const int*)  d_in[1];
    const int*   edst   = (const int*)  d_in[2];
    const float* degree = (const float*)d_in[3];
    const float* sn_g   = (const float*)d_in[4];
    const float* sn_b   = (const float*)d_in[5];
    const float* nn_g   = (const float*)d_in[6];
    const float* nn_b   = (const float*)d_in[7];
    const float* W1     = (const float*)d_in[8];
    const float* b1     = (const float*)d_in[9];
    const float* W2     = (const float*)d_in[10];
    const float* b2     = (const float*)d_in[11];

    const int E     = in_sizes[1];
    const int nrows = in_sizes[0] / D;   // B*N
    const int N     = in_sizes[3];
    const int nb    = (N + 1023) / 1024;

    prep_scan_kernel<<<12 + nb, 1024>>>(W1, W2, degree, N);
    scan2_kernel<<<1, 64>>>(nb);
    fill_kernel<<<(E + 255) / 256, 256>>>(esrc, edst, E);

    cudaFuncSetAttribute(fused_kernel, cudaFuncAttributeMaxDynamicSharedMemorySize, SMEM_TOTAL);
    fused_kernel<<<(nrows + MTILE - 1) / MTILE, NTHREADS, SMEM_TOTAL>>>(
        x, degree, sn_g, sn_b, nn_g, nn_b, b1, b2, (float*)d_out, N, nrows);
}